// round 8
// baseline (speedup 1.0000x reference)
#include <cuda_runtime.h>
#include <cuda_bf16.h>

#define ULL unsigned long long

__device__ __forceinline__ ULL add2(ULL a, ULL b) {
    ULL r; asm("add.rn.f32x2 %0, %1, %2;" : "=l"(r) : "l"(a), "l"(b)); return r;
}
__device__ __forceinline__ void unpk2(ULL v, float& lo, float& hi) {
    asm("mov.b64 {%0, %1}, %2;" : "=f"(lo), "=f"(hi) : "l"(v));
}

// Codebook-resident, warp-private-softmax design.
// grid = #SMs, 1 block/SM, 512 threads (16 warps).
// Codebook (512 cells x 64 dims = 128 KB) staged into smem ONCE.
// 1024 tiles of 8 states (4% wave imbalance vs 19% at 32-state tiles).
// Warp w: state = w>>1, cell half = w&1 (256 cells), lane handles 8 cells
// (stride 32). acc = 8 ULL = 16 regs -> ~50 regs total, deep LDS batching.
// Softmax: per-warp partial (m, s) + single smem merge with partner warp.
// x staged NEGATED so the inner loop is pure FADD2 + LOP3 + LDS.
__global__ __launch_bounds__(512, 1) void PlaceCells_kernel(
    const float* __restrict__ x, const float* __restrict__ pc,
    float* __restrict__ out, int nblocks)
{
    extern __shared__ char smem[];
    float4* cs4 = reinterpret_cast<float4*>(smem);             // [16 dq][512 cells] = 128 KB
    float4* xs4 = reinterpret_cast<float4*>(smem + 131072);    // [8 states][16 dq] = 2 KB

    __shared__ float wm[16];
    __shared__ float ws[16];

    const int tid   = threadIdx.x;
    const int lane  = tid & 31;
    const int w     = tid >> 5;       // 0..15
    const int stloc = w >> 1;         // local state 0..7
    const int hv    = w & 1;          // cell half: cells hv*256 + lane + j*32

    // ---- stage full codebook once: cs4[dq*512 + cell] (conflict-free STS) ----
    const float4* pc4 = reinterpret_cast<const float4*>(pc);
    #pragma unroll
    for (int i = 0; i < 16; i++)
        cs4[i * 512 + tid] = pc4[tid * 16 + i];

    const float4* x4 = reinterpret_cast<const float4*>(x);
    const ulonglong2* csU = reinterpret_cast<const ulonglong2*>(cs4);
    const ulonglong2* xsU = reinterpret_cast<const ulonglong2*>(xs4);
    const ULL ABSM = 0x7FFFFFFF7FFFFFFFULL;

    for (int tile = blockIdx.x; tile < 1024; tile += nblocks) {
        const int bs = tile * 8;

        // ---- stage -x for this tile: 8 states x 16 dq = 128 float4 ----
        if (tid < 128) {
            int s = tid >> 4, q = tid & 15;
            float4 v = x4[(ULL)(bs + s) * 16 + q];
            xs4[tid] = make_float4(-v.x, -v.y, -v.z, -v.w);
        }
        __syncthreads();   // xs4 visible (covers codebook on first tile)

        // ---- barrier-free mainloop: 8 independent chains per thread ----
        ULL acc[8];
        #pragma unroll
        for (int j = 0; j < 8; j++) acc[j] = 0ULL;

        #pragma unroll 4
        for (int dq = 0; dq < 16; dq++) {
            ulonglong2 nx = xsU[stloc * 16 + dq];   // warp-uniform broadcast
            #pragma unroll
            for (int j = 0; j < 8; j++) {
                ulonglong2 cv = csU[dq * 512 + hv * 256 + j * 32 + lane]; // conflict-free
                ULL d0 = add2(cv.x, nx.x) & ABSM;   // |c - x| on 2 dims
                ULL d1 = add2(cv.y, nx.y) & ABSM;
                acc[j] = add2(acc[j], d0);
                acc[j] = add2(acc[j], d1);
            }
        }

        // ---- logits u = -0.5 * l1^2 ----
        float u[8];
        #pragma unroll
        for (int j = 0; j < 8; j++) {
            float lo, hi; unpk2(acc[j], lo, hi);
            float l1 = lo + hi;
            u[j] = -0.5f * l1 * l1;
        }

        // ---- warp-partial max ----
        float m = u[0];
        #pragma unroll
        for (int j = 1; j < 8; j++) m = fmaxf(m, u[j]);
        #pragma unroll
        for (int off = 16; off > 0; off >>= 1)
            m = fmaxf(m, __shfl_xor_sync(0xffffffffu, m, off));

        // ---- warp-partial sum of exp(u - m) ----
        float s = 0.0f;
        #pragma unroll
        for (int j = 0; j < 8; j++) s += __expf(u[j] - m);
        #pragma unroll
        for (int off = 16; off > 0; off >>= 1)
            s += __shfl_xor_sync(0xffffffffu, s, off);

        if (lane == 0) { wm[w] = m; ws[w] = s; }
        __syncthreads();

        // ---- merge with partner warp (other 256 cells of same state) ----
        float mo = wm[w ^ 1], so = ws[w ^ 1];
        float M   = fmaxf(m, mo);
        float tot = s * __expf(m - M) + so * __expf(mo - M);
        float inv = 1.0f / tot;

        const ULL srow = (ULL)(bs + stloc);
        #pragma unroll
        for (int j = 0; j < 8; j++)
            out[srow * 512 + hv * 256 + j * 32 + lane] = __expf(u[j] - M) * inv;
        // next tile's xs4 staging is safe after this point: all warps passed
        // the merge barrier, so all xs4/wm/ws reads of this tile are done
        // before any thread re-stages (visibility enforced by the top barrier).
    }
}

extern "C" void kernel_launch(void* const* d_in, const int* in_sizes, int n_in,
                              void* d_out, int out_size) {
    const float* a = (const float*)d_in[0];
    const float* b = (const float*)d_in[1];
    // x is the larger tensor (8192*64), placeCells is 512*64
    const float* x  = (in_sizes[0] >= in_sizes[1]) ? a : b;
    const float* pc = (in_sizes[0] >= in_sizes[1]) ? b : a;

    const int dyn_smem = 131072 + 2048;   // codebook 128 KB + x tile 2 KB

    static int nsm = 0;
    if (!nsm) {
        cudaDeviceGetAttribute(&nsm, cudaDevAttrMultiProcessorCount, 0);
        if (nsm <= 0) nsm = 148;
        cudaFuncSetAttribute(PlaceCells_kernel,
                             cudaFuncAttributeMaxDynamicSharedMemorySize, dyn_smem);
    }
    PlaceCells_kernel<<<nsm, 512, dyn_smem>>>(x, pc, (float*)d_out, nsm);
}

// round 9
// speedup vs baseline: 1.1424x; 1.1424x over previous
#include <cuda_runtime.h>
#include <cuda_bf16.h>

#define ULL unsigned long long

__device__ __forceinline__ ULL add2(ULL a, ULL b) {
    ULL r; asm("add.rn.f32x2 %0, %1, %2;" : "=l"(r) : "l"(a), "l"(b)); return r;
}
__device__ __forceinline__ void unpk2(ULL v, float& lo, float& hi) {
    asm("mov.b64 {%0, %1}, %2;" : "=f"(lo), "=f"(hi) : "l"(v));
}

// Codebook-resident persistent design, v9.
// grid = #SMs, 1 block/SM, 1024 threads (32 warps, 8/SMSP).
// Codebook (512 cells x 64 dims = 128 KB) staged into smem ONCE.
// 1024 tiles of 8 states -> 4% wave imbalance.
// Thread: state-quad q4 = (tid>>9)*4 (4 states), cell c = tid & 511.
// Each cv LDS.128 (4 dims of one cell) feeds 4 states => 16 elems/LDS,
// smem crossbar ~50% (R8 failure mode was 1 state/LDS => crossbar-bound).
// acc = 4 ULL = 8 regs; x staged NEGATED so inner loop = FADD2 + LOP3 + LDS.
__global__ __launch_bounds__(1024, 1) void PlaceCells_kernel(
    const float* __restrict__ x, const float* __restrict__ pc,
    float* __restrict__ out, int nblocks)
{
    extern __shared__ char smem[];
    float4* cs4 = reinterpret_cast<float4*>(smem);             // [16 dq][512 cells] = 128 KB
    float4* xs4 = reinterpret_cast<float4*>(smem + 131072);    // [8 states][16 dq] = 2 KB

    __shared__ float wm[8][16];   // per-state, per-cell-group-of-32 partial max
    __shared__ float ws[8][16];   // partial sum

    const int tid  = threadIdx.x;
    const int lane = tid & 31;
    const int w    = tid >> 5;        // 0..31
    const int c    = tid & 511;       // cell  = (w&15)*32 + lane
    const int q4   = (tid >> 9) * 4;  // first state of this thread's quad
    const int w16  = w & 15;

    // ---- stage full codebook once: cs4[dq*512 + cell] ----
    const float4* pc4 = reinterpret_cast<const float4*>(pc);
    {
        const int half = tid >> 9;            // 0/1: dqs 0-7 vs 8-15
        #pragma unroll
        for (int k = 0; k < 8; k++) {
            int i = half * 8 + k;
            cs4[i * 512 + c] = pc4[c * 16 + i];
        }
    }

    const float4* x4 = reinterpret_cast<const float4*>(x);
    const ulonglong2* csU = reinterpret_cast<const ulonglong2*>(cs4);
    const ulonglong2* xsU = reinterpret_cast<const ulonglong2*>(xs4);
    const ULL ABSM = 0x7FFFFFFF7FFFFFFFULL;

    for (int tile = blockIdx.x; tile < 1024; tile += nblocks) {
        const int bs = tile * 8;

        // ---- stage -x for this tile: 8 states x 16 dq = 128 float4 ----
        // (safe: all reads of xs4 from the previous tile finished before the
        //  previous tile's post-partial barrier, which everyone has passed)
        if (tid < 128) {
            int s = tid >> 4, qq = tid & 15;
            float4 v = x4[(ULL)(bs + s) * 16 + qq];
            xs4[tid] = make_float4(-v.x, -v.y, -v.z, -v.w);
        }
        __syncthreads();   // xs4 (and codebook, first tile) visible

        // ---- barrier-free mainloop ----
        ULL acc[4];
        #pragma unroll
        for (int i = 0; i < 4; i++) acc[i] = 0ULL;

        #pragma unroll 8
        for (int dq = 0; dq < 16; dq++) {
            ulonglong2 cv = csU[dq * 512 + c];          // conflict-free, feeds 4 states
            #pragma unroll
            for (int i = 0; i < 4; i++) {
                ulonglong2 nx = xsU[(q4 + i) * 16 + dq]; // warp-uniform broadcast
                ULL d0 = add2(cv.x, nx.x) & ABSM;       // |c - x| on 2 dims
                ULL d1 = add2(cv.y, nx.y) & ABSM;
                acc[i] = add2(acc[i], d0);
                acc[i] = add2(acc[i], d1);
            }
        }

        // ---- logits u = -0.5 * l1^2 ----
        float u[4];
        #pragma unroll
        for (int i = 0; i < 4; i++) {
            float lo, hi; unpk2(acc[i], lo, hi);
            float l1 = lo + hi;
            u[i] = -0.5f * l1 * l1;
        }

        // ---- warp partials: max + sum over this warp's 32 cells, per state ----
        #pragma unroll
        for (int i = 0; i < 4; i++) {
            float m = u[i];
            #pragma unroll
            for (int off = 16; off > 0; off >>= 1)
                m = fmaxf(m, __shfl_xor_sync(0xffffffffu, m, off));
            float s = __expf(u[i] - m);
            #pragma unroll
            for (int off = 16; off > 0; off >>= 1)
                s += __shfl_xor_sync(0xffffffffu, s, off);
            if (lane == 0) { wm[q4 + i][w16] = m; ws[q4 + i][w16] = s; }
        }
        __syncthreads();   // all partials visible

        // ---- merge 16 partials per state (warp-parallel, duplicated halves) ----
        #pragma unroll
        for (int i = 0; i < 4; i++) {
            const int st = q4 + i;
            float pm = wm[st][lane & 15];
            float pM = pm;
            #pragma unroll
            for (int off = 8; off > 0; off >>= 1)
                pM = fmaxf(pM, __shfl_xor_sync(0xffffffffu, pM, off));
            float ps = ws[st][lane & 15] * __expf(pm - pM);
            #pragma unroll
            for (int off = 8; off > 0; off >>= 1)
                ps += __shfl_xor_sync(0xffffffffu, ps, off);
            float inv = 1.0f / ps;
            out[(ULL)(bs + st) * 512 + c] = __expf(u[i] - pM) * inv;
        }
    }
}

extern "C" void kernel_launch(void* const* d_in, const int* in_sizes, int n_in,
                              void* d_out, int out_size) {
    const float* a = (const float*)d_in[0];
    const float* b = (const float*)d_in[1];
    // x is the larger tensor (8192*64), placeCells is 512*64
    const float* x  = (in_sizes[0] >= in_sizes[1]) ? a : b;
    const float* pc = (in_sizes[0] >= in_sizes[1]) ? b : a;

    const int dyn_smem = 131072 + 2048;   // codebook 128 KB + x tile 2 KB

    static int nsm = 0;
    if (!nsm) {
        cudaDeviceGetAttribute(&nsm, cudaDevAttrMultiProcessorCount, 0);
        if (nsm <= 0) nsm = 148;
        cudaFuncSetAttribute(PlaceCells_kernel,
                             cudaFuncAttributeMaxDynamicSharedMemorySize, dyn_smem);
    }
    PlaceCells_kernel<<<nsm, 1024, dyn_smem>>>(x, pc, (float*)d_out, nsm);
}

// round 11
// speedup vs baseline: 1.5154x; 1.3265x over previous
#include <cuda_runtime.h>
#include <cuda_bf16.h>

#define ULL unsigned long long

__device__ __forceinline__ ULL add2(ULL a, ULL b) {
    ULL r; asm("add.rn.f32x2 %0, %1, %2;" : "=l"(r) : "l"(a), "l"(b)); return r;
}
__device__ __forceinline__ void unpk2(ULL v, float& lo, float& hi) {
    asm("mov.b64 {%0, %1}, %2;" : "=f"(lo), "=f"(hi) : "l"(v));
}
__device__ __forceinline__ void barw(int id) {   // worker-scoped named barrier, 128 threads
    asm volatile("bar.sync %0, 128;" :: "r"(id) : "memory");
}

// v10: codebook-resident + sub-block workers + fine quanta.
// grid = #SMs, 1 block/SM, 768 threads = 6 workers x 128 threads (4 warps each;
// worker warps land 1 per SMSP). Codebook (128 KB) staged once.
// Quantum = 4 states x 512 cells; 2048 quanta assigned round-robin to BLOCKS
// (13-14 per SM, 4% skew), then round-robin to workers within the block.
// Thread tile S=4 states x C=4 cells -> LDS:pipe ratio 0.083 (R7-class, keeps
// smem port < ~45%). acc = 16 ULL = 32 regs. Steady state uses only worker-scoped
// named barriers (2 per quantum) -- no block-wide sync after the prologue.
// x staged NEGATED so the inner loop is pure FADD2 + LOP3 + LDS.
__global__ __launch_bounds__(768, 1) void PlaceCells_kernel(
    const float* __restrict__ x, const float* __restrict__ pc,
    float* __restrict__ out, int nblocks)
{
    extern __shared__ char smem[];
    float4* cs4 = reinterpret_cast<float4*>(smem);            // [16 dq][512 cells] = 128 KB
    float4* xsw = reinterpret_cast<float4*>(smem + 131072);   // [6 workers][4 st][16 dq] = 6 KB
    float*  wmp = reinterpret_cast<float*>(smem + 131072 + 6144);          // [6][4 warp][4 st]
    float*  wsp = reinterpret_cast<float*>(smem + 131072 + 6144 + 384);    // [6][4 warp][4 st]

    const int tid  = threadIdx.x;
    const int wk   = tid >> 7;        // worker 0..5
    const int wt   = tid & 127;       // thread-in-worker (= cell-thread tc)
    const int lane = tid & 31;
    const int ww   = wt >> 5;         // warp-in-worker 0..3

    // ---- stage full codebook once: cs4[dq*512 + cell] (conflict-free STS) ----
    if (tid < 512) {
        const float4* pc4 = reinterpret_cast<const float4*>(pc);
        #pragma unroll
        for (int i = 0; i < 16; i++)
            cs4[i * 512 + tid] = pc4[tid * 16 + i];
    }
    __syncthreads();    // only block-wide barrier in the kernel

    const float4* x4 = reinterpret_cast<const float4*>(x);
    const ulonglong2* csU = reinterpret_cast<const ulonglong2*>(cs4);
    const ulonglong2* xwU = reinterpret_cast<const ulonglong2*>(xsw) + wk * 64; // [4 st][16 dq]
    float4* myxs = xsw + wk * 64;
    const ULL ABSM = 0x7FFFFFFF7FFFFFFFULL;
    const int bid = blockIdx.x;

    // quanta of this block: q = bid + 152*m ; m-th one goes to worker m%6
    for (int m = wk; ; m += 6) {
        const int q = bid + nblocks * m;
        if (q >= 2048) break;
        const int bs = q * 4;           // first state of quantum

        // ---- stage -x for this quantum: 4 states x 16 dq = 64 float4 ----
        if (wt < 64) {
            int s = wt >> 4, qq = wt & 15;
            float4 v = x4[(ULL)(bs + s) * 16 + qq];
            myxs[wt] = make_float4(-v.x, -v.y, -v.z, -v.w);
        }
        barw(wk + 1);   // xs visible to worker; also guards vs prev quantum's reads

        // ---- mainloop: S=4 states x C=4 cells per thread ----
        ULL acc[4][4];
        #pragma unroll
        for (int i = 0; i < 4; i++)
            #pragma unroll
            for (int j = 0; j < 4; j++) acc[i][j] = 0ULL;

        #pragma unroll 4
        for (int dq = 0; dq < 16; dq++) {
            ulonglong2 nx[4];
            #pragma unroll
            for (int i = 0; i < 4; i++)
                nx[i] = xwU[i * 16 + dq];               // warp-uniform broadcast
            #pragma unroll
            for (int j = 0; j < 4; j++) {
                ulonglong2 cv = csU[dq * 512 + wt + j * 128];   // conflict-free
                #pragma unroll
                for (int i = 0; i < 4; i++) {
                    ULL d0 = add2(cv.x, nx[i].x) & ABSM;   // |c - x| on 2 dims
                    ULL d1 = add2(cv.y, nx[i].y) & ABSM;
                    acc[i][j] = add2(acc[i][j], d0);
                    acc[i][j] = add2(acc[i][j], d1);
                }
            }
        }

        // ---- logits u = -0.5 * l1^2 ----
        float u[4][4];
        #pragma unroll
        for (int i = 0; i < 4; i++)
            #pragma unroll
            for (int j = 0; j < 4; j++) {
                float lo, hi; unpk2(acc[i][j], lo, hi);
                float l1 = lo + hi;
                u[i][j] = -0.5f * l1 * l1;
            }

        // ---- per-warp partial (m, s) per state over this warp's 128 cells ----
        #pragma unroll
        for (int i = 0; i < 4; i++) {
            float pm = fmaxf(fmaxf(u[i][0], u[i][1]), fmaxf(u[i][2], u[i][3]));
            #pragma unroll
            for (int off = 16; off > 0; off >>= 1)
                pm = fmaxf(pm, __shfl_xor_sync(0xffffffffu, pm, off));
            float ps = __expf(u[i][0] - pm) + __expf(u[i][1] - pm)
                     + __expf(u[i][2] - pm) + __expf(u[i][3] - pm);
            #pragma unroll
            for (int off = 16; off > 0; off >>= 1)
                ps += __shfl_xor_sync(0xffffffffu, ps, off);
            if (lane == 0) {
                wmp[(wk * 4 + ww) * 4 + i] = pm;
                wsp[(wk * 4 + ww) * 4 + i] = ps;
            }
        }
        barw(wk + 1);   // partials visible within worker

        // ---- merge 4 warp-partials per state, write output ----
        #pragma unroll
        for (int i = 0; i < 4; i++) {
            float m0 = wmp[(wk * 4 + 0) * 4 + i], s0 = wsp[(wk * 4 + 0) * 4 + i];
            float m1 = wmp[(wk * 4 + 1) * 4 + i], s1 = wsp[(wk * 4 + 1) * 4 + i];
            float m2 = wmp[(wk * 4 + 2) * 4 + i], s2 = wsp[(wk * 4 + 2) * 4 + i];
            float m3 = wmp[(wk * 4 + 3) * 4 + i], s3 = wsp[(wk * 4 + 3) * 4 + i];
            float M = fmaxf(fmaxf(m0, m1), fmaxf(m2, m3));
            float S = s0 * __expf(m0 - M) + s1 * __expf(m1 - M)
                    + s2 * __expf(m2 - M) + s3 * __expf(m3 - M);
            float inv = 1.0f / S;
            const ULL srow = (ULL)(bs + i);
            #pragma unroll
            for (int j = 0; j < 4; j++)
                out[srow * 512 + wt + j * 128] = __expf(u[i][j] - M) * inv;
        }
    }
}

extern "C" void kernel_launch(void* const* d_in, const int* in_sizes, int n_in,
                              void* d_out, int out_size) {
    const float* a = (const float*)d_in[0];
    const float* b = (const float*)d_in[1];
    // x is the larger tensor (8192*64), placeCells is 512*64
    const float* x  = (in_sizes[0] >= in_sizes[1]) ? a : b;
    const float* pc = (in_sizes[0] >= in_sizes[1]) ? b : a;

    const int dyn_smem = 131072 + 6144 + 768;  // codebook + x tiles + partials

    static int nsm = 0;
    if (!nsm) {
        cudaDeviceGetAttribute(&nsm, cudaDevAttrMultiProcessorCount, 0);
        if (nsm <= 0) nsm = 148;
        cudaFuncSetAttribute(PlaceCells_kernel,
                             cudaFuncAttributeMaxDynamicSharedMemorySize, dyn_smem);
    }
    PlaceCells_kernel<<<nsm, 768, dyn_smem>>>(x, pc, (float*)d_out, nsm);
}